// round 16
// baseline (speedup 1.0000x reference)
#include <cuda_runtime.h>
#include <cstdint>

#define BATCHN 64
#define SEQN   512
#define EMBN   256
#define HN     256
#define G4N    1024   // 4*H
#define NCOL   2048   // both directions' gate columns
#define NLAB   10

// ---------------- scratch (device globals; no runtime allocation) ----------
__device__ float g_zx[(size_t)SEQN * BATCHN * NCOL];   // [t][b][col2]  (268 MB)
__device__ float g_h[2][HN][BATCHN];                   // final h only [dir][u][b]

// ---------------- f32x2 helpers -------------------------------------------
__device__ __forceinline__ uint64_t pack2(float lo, float hi) {
    uint64_t r;
    asm("mov.b64 %0, {%1, %2};" : "=l"(r)
        : "r"(__float_as_uint(lo)), "r"(__float_as_uint(hi)));
    return r;
}
__device__ __forceinline__ void unpack2(uint64_t v, float& lo, float& hi) {
    unsigned a, b;
    asm("mov.b64 {%0, %1}, %2;" : "=r"(a), "=r"(b) : "l"(v));
    lo = __uint_as_float(a); hi = __uint_as_float(b);
}
__device__ __forceinline__ uint64_t ffma2(uint64_t a, uint64_t b, uint64_t c) {
    uint64_t d;
    asm("fma.rn.f32x2 %0, %1, %2, %3;" : "=l"(d) : "l"(a), "l"(b), "l"(c));
    return d;
}
__device__ __forceinline__ uint64_t addf2(uint64_t a, uint64_t b) {
    uint64_t d;
    asm("add.rn.f32x2 %0, %1, %2;" : "=l"(d) : "l"(a), "l"(b));
    return d;
}
__device__ __forceinline__ uint64_t ldg64(const void* p) {
    uint64_t v;
    asm volatile("ld.global.nc.b64 %0, [%1];" : "=l"(v) : "l"(p));
    return v;
}
__device__ __forceinline__ uint32_t smem_u32(const void* p) {
    uint32_t a;
    asm("{ .reg .u64 t; cvta.to.shared.u64 t, %1; cvt.u32.u64 %0, t; }"
        : "=r"(a) : "l"(p));
    return a;
}

__device__ __forceinline__ float sigf(float x) {
    return __fdividef(1.0f, 1.0f + __expf(-x));
}
__device__ __forceinline__ float tanhfast(float x) {
    float e = __expf(2.0f * x);
    return 1.0f - 2.0f * __fdividef(1.0f, e + 1.0f);
}

// ============================================================================
// Kernel 1: zx = gather(emb, tokens) @ [Wx_f||Wx_b] + bias  (proven r14)
// ============================================================================
__global__ void __launch_bounds__(256, 2) zx_gemm_kernel(
    const int*   __restrict__ tokens,
    const float* __restrict__ emb,
    const float* __restrict__ Wx_f, const float* __restrict__ b_f,
    const float* __restrict__ Wx_b, const float* __restrict__ b_b)
{
    __shared__ uint64_t a2_s[32 * 64];
    __shared__ float    b_s[32][128];
    __shared__ int      tok_s[128];

    const int tid    = threadIdx.x;
    const int mtile  = blockIdx.x >> 4;
    const int ntile  = blockIdx.x & 15;
    const int n2base = ntile * 128;
    const float* wsrc = (n2base < G4N) ? (Wx_f + n2base) : (Wx_b + (n2base - G4N));

    if (tid < 128) {
        int gm = mtile * 128 + tid;
        tok_s[tid] = tokens[(gm & 63) * SEQN + (gm >> 6)];
    }
    __syncthreads();

    const int mp0 = (tid & 15) * 4;
    const int n0  = (tid >> 4) * 8;

    uint64_t acc[4][8];
#pragma unroll
    for (int p = 0; p < 4; ++p)
#pragma unroll
        for (int j = 0; j < 8; ++j) acc[p][j] = 0ull;

    for (int kc = 0; kc < 8; ++kc) {
        const int kbase = kc * 32;
        if (kc) __syncthreads();

#pragma unroll
        for (int i = 0; i < 2; ++i) {
            int task = tid + i * 256;
            int mp   = task & 63;
            int col4 = task >> 6;
            const float* r0 = emb + (size_t)tok_s[2*mp]   * EMBN + kbase + col4*4;
            const float* r1 = emb + (size_t)tok_s[2*mp+1] * EMBN + kbase + col4*4;
            float4 va = *(const float4*)r0;
            float4 vb = *(const float4*)r1;
            a2_s[(col4*4 + 0) * 64 + mp] = pack2(va.x, vb.x);
            a2_s[(col4*4 + 1) * 64 + mp] = pack2(va.y, vb.y);
            a2_s[(col4*4 + 2) * 64 + mp] = pack2(va.z, vb.z);
            a2_s[(col4*4 + 3) * 64 + mp] = pack2(va.w, vb.w);
        }
#pragma unroll
        for (int i = 0; i < 4; ++i) {
            int f4  = tid + i * 256;
            int row = f4 >> 5;
            int c4  = f4 & 31;
            *(float4*)&b_s[row][c4 * 4] =
                *(const float4*)(wsrc + (size_t)(kbase + row) * G4N + c4 * 4);
        }
        __syncthreads();

#pragma unroll 4
        for (int k = 0; k < 32; ++k) {
            const uint64_t* ak = a2_s + k * 64 + mp0;
            ulonglong2 a01 = *(const ulonglong2*)ak;
            ulonglong2 a23 = *(const ulonglong2*)(ak + 2);
            float4 bv0 = *(const float4*)&b_s[k][n0];
            float4 bv1 = *(const float4*)&b_s[k][n0 + 4];
            uint64_t bb0 = pack2(bv0.x, bv0.x);
            uint64_t bb1 = pack2(bv0.y, bv0.y);
            uint64_t bb2 = pack2(bv0.z, bv0.z);
            uint64_t bb3 = pack2(bv0.w, bv0.w);
            uint64_t bb4 = pack2(bv1.x, bv1.x);
            uint64_t bb5 = pack2(bv1.y, bv1.y);
            uint64_t bb6 = pack2(bv1.z, bv1.z);
            uint64_t bb7 = pack2(bv1.w, bv1.w);
#pragma unroll
            for (int p = 0; p < 4; ++p) {
                uint64_t av = (p == 0) ? a01.x : (p == 1) ? a01.y
                             : (p == 2) ? a23.x : a23.y;
                acc[p][0] = ffma2(av, bb0, acc[p][0]);
                acc[p][1] = ffma2(av, bb1, acc[p][1]);
                acc[p][2] = ffma2(av, bb2, acc[p][2]);
                acc[p][3] = ffma2(av, bb3, acc[p][3]);
                acc[p][4] = ffma2(av, bb4, acc[p][4]);
                acc[p][5] = ffma2(av, bb5, acc[p][5]);
                acc[p][6] = ffma2(av, bb6, acc[p][6]);
                acc[p][7] = ffma2(av, bb7, acc[p][7]);
            }
        }
    }

    float bias[8];
#pragma unroll
    for (int j = 0; j < 8; ++j) {
        int col2 = n2base + n0 + j;
        bias[j] = (col2 < G4N) ? b_f[col2] : b_b[col2 - G4N];
    }
#pragma unroll
    for (int p = 0; p < 4; ++p) {
        float lo[8], hi[8];
#pragma unroll
        for (int j = 0; j < 8; ++j) {
            unpack2(acc[p][j], lo[j], hi[j]);
            lo[j] += bias[j]; hi[j] += bias[j];
        }
        size_t m = (size_t)(mtile * 128 + 2 * (mp0 + p));
        float* dst = g_zx + m * NCOL + n2base + n0;
        *(float4*)(dst)            = make_float4(lo[0], lo[1], lo[2], lo[3]);
        *(float4*)(dst + 4)        = make_float4(lo[4], lo[5], lo[6], lo[7]);
        *(float4*)(dst + NCOL)     = make_float4(hi[0], hi[1], hi[2], hi[3]);
        *(float4*)(dst + NCOL + 4) = make_float4(hi[4], hi[5], hi[6], hi[7]);
    }
}

// ============================================================================
// Kernel 2: cluster-resident bidirectional LSTM.  One launch, all 512 steps.
// 16 chains = (dir 2) x (batch-eighth 8); chain == one 8-CTA cluster.
// CTA (cluster rank r) owns units [r*32, r*32+32) for its chain's 8 batches.
// 256 threads = js(2) x upair(16) x b(8); FFMA2 packs over UNIT pairs so the
// 128 KB Wh slice needs NO duplication in smem.
// Per-step sync = one split cluster barrier (arrive end-of-step, wait at
// next step's consume point); h exchanged via DSMEM (pull 1 KB per rank,
// expand to duplicated h_dup in own smem).  No L2 flags, no grid barrier.
// smem: w2 128K | h_dup 16K | pub 2K | red 4K = 150 KB dynamic, 1 CTA/SM.
// ============================================================================
__global__ void __launch_bounds__(256)
__cluster_dims__(8, 1, 1)
lstm_kernel(const float* __restrict__ Wh_f, const float* __restrict__ Wh_b)
{
    extern __shared__ unsigned char smraw[];
    uint64_t* w2   = (uint64_t*)smraw;                     // [j][up][g] {w_u0,w_u1} 128 KB
    uint64_t* h_dup = (uint64_t*)(smraw + 131072);         // [j][b] {h,h}          16 KB
    float*    pub  = (float*)(smraw + 147456);             // [par][u32][b8]         2 KB
    uint64_t* red  = (uint64_t*)(smraw + 149504);          // [upb][g]               4 KB

    const int tid = threadIdx.x;
    const int cl  = blockIdx.x >> 3;       // cluster id 0..15
    const int dir = cl >> 3;               // 0 fwd, 1 bwd
    const int bq  = cl & 7;                // batch-eighth
    uint32_t rank;
    asm("mov.u32 %0, %%cluster_ctarank;" : "=r"(rank));
    const int u0  = (int)rank * 32;        // this CTA's unit base
    const int B0g = bq * 8;                // global batch base
    const float* Wh = dir ? Wh_b : Wh_f;

    // ---- one-time: stage packed Wh slice: w2[(j*16+up)*4+g] = {Wh[j][g*256+u0+2up], +1}
    for (int idx = tid; idx < HN * 16 * 4; idx += 256) {
        int j  = idx >> 6;
        int up = (idx >> 2) & 15;
        int g  = idx & 3;
        w2[idx] = *(const uint64_t*)&Wh[(size_t)j * G4N + g * HN + u0 + 2 * up];
    }

    const int js = tid >> 7;               // j-half
    const int r7 = tid & 127;
    const int b  = r7 & 7;                 // local batch 0..7
    const int up = r7 >> 3;                // unit pair 0..15
    const int jbase = js * 128;
    const uint64_t* wp = w2 + up * 4;
    uint64_t* rslot = red + r7 * 4;

    // pull assignment: thread tid stages source-unit row u = tid (0..255)
    const int pu   = tid;                  // source unit (j index)
    const int prk  = pu >> 5;              // producer rank
    const uint32_t pub_base = smem_u32(pub);
    const uint32_t plofs = (uint32_t)(pu & 31) * 32;   // row offset in producer pub

    float c0 = 0.0f, c1 = 0.0f;            // cell state for (u0+2up, u0+2up+1), batch b

    __syncthreads();   // w2 staged

    for (int t = 0; t < SEQN; ++t) {
        const int zt = dir ? (SEQN - 1 - t) : t;
        // z preloads (js=0): {u_even,u_odd} pairs load as b64 — match acc lanes
        uint64_t zv0, zv1, zv2, zv3;
        if (js == 0) {
            const float* zrow = g_zx + ((size_t)zt * BATCHN + B0g + b) * NCOL
                                     + dir * G4N + u0 + 2 * up;
            zv0 = ldg64(zrow + 0 * HN);
            zv1 = ldg64(zrow + 1 * HN);
            zv2 = ldg64(zrow + 2 * HN);
            zv3 = ldg64(zrow + 3 * HN);
        }

        uint64_t ai = 0ull, af = 0ull, ag = 0ull, ao = 0ull;

        if (t > 0) {
            // wait: all cluster CTAs finished step t-1 (published h_t);
            // acquire semantics -> peer pub writes visible
            asm volatile("barrier.cluster.wait.aligned;" ::: "memory");

            // pull h_t rows from peers via DSMEM, expand {h,h} into h_dup
            {
                const int par = t & 1;
                uint32_t src = pub_base + (uint32_t)par * 1024 + plofs;
                uint32_t pa;
                asm("mapa.shared::cluster.u32 %0, %1, %2;"
                    : "=r"(pa) : "r"(src), "r"(prk));
                float x0, x1, x2, x3, x4, x5, x6, x7;
                asm volatile("ld.shared::cluster.v4.f32 {%0,%1,%2,%3}, [%4];"
                    : "=f"(x0), "=f"(x1), "=f"(x2), "=f"(x3) : "r"(pa));
                asm volatile("ld.shared::cluster.v4.f32 {%0,%1,%2,%3}, [%4];"
                    : "=f"(x4), "=f"(x5), "=f"(x6), "=f"(x7) : "r"(pa + 16));
                uint64_t* dst = h_dup + pu * 8;
                ulonglong2 d01, d23, d45, d67;
                d01.x = pack2(x0, x0); d01.y = pack2(x1, x1);
                d23.x = pack2(x2, x2); d23.y = pack2(x3, x3);
                d45.x = pack2(x4, x4); d45.y = pack2(x5, x5);
                d67.x = pack2(x6, x6); d67.y = pack2(x7, x7);
                *(ulonglong2*)(dst + 0) = d01;
                *(ulonglong2*)(dst + 2) = d23;
                *(ulonglong2*)(dst + 4) = d45;
                *(ulonglong2*)(dst + 6) = d67;
            }
            __syncthreads();   // full h_dup staged

#pragma unroll 8
            for (int j = 0; j < 128; ++j) {
                const int jj = jbase + j;
                uint64_t h2 = h_dup[jj * 8 + b];
                ulonglong2 w01 = *(const ulonglong2*)(wp + jj * 64);
                ulonglong2 w23 = *(const ulonglong2*)(wp + jj * 64 + 2);
                ai = ffma2(h2, w01.x, ai);
                af = ffma2(h2, w01.y, af);
                ag = ffma2(h2, w23.x, ag);
                ao = ffma2(h2, w23.y, ao);
            }
        }

        // reduce js=1 partials into js=0
        if (js == 1) {
            rslot[0] = ai; rslot[1] = af; rslot[2] = ag; rslot[3] = ao;
        }
        __syncthreads();
        if (js == 0) {
            ai = addf2(addf2(ai, rslot[0]), zv0);
            af = addf2(addf2(af, rslot[1]), zv1);
            ag = addf2(addf2(ag, rslot[2]), zv2);
            ao = addf2(addf2(ao, rslot[3]), zv3);

            float i0, i1, f0, f1, g0, g1, o0, o1;
            unpack2(ai, i0, i1); unpack2(af, f0, f1);
            unpack2(ag, g0, g1); unpack2(ao, o0, o1);

            float I0 = sigf(i0), F0 = sigf(f0), Gt0 = tanhfast(g0), O0 = sigf(o0);
            float I1 = sigf(i1), F1 = sigf(f1), Gt1 = tanhfast(g1), O1 = sigf(o1);
            c0 = F0 * c0 + I0 * Gt0;
            c1 = F1 * c1 + I1 * Gt1;
            float h0 = O0 * tanhfast(c0);
            float h1 = O1 * tanhfast(c1);

            // publish h_{t+1} into own pub buffer (parity (t+1)&1)
            const int par = (t + 1) & 1;
            pub[par * 256 + (2 * up)     * 8 + b] = h0;
            pub[par * 256 + (2 * up + 1) * 8 + b] = h1;

            if (t == SEQN - 1) {
                g_h[dir][u0 + 2 * up][B0g + b]     = h0;
                g_h[dir][u0 + 2 * up + 1][B0g + b] = h1;
            }
        }
        __syncthreads();   // pub writes done CTA-wide before release-arrive
        asm volatile("barrier.cluster.arrive.aligned;" ::: "memory");
    }

    // match the final arrive
    asm volatile("barrier.cluster.wait.aligned;" ::: "memory");
}

// ============================================================================
// Kernel 3: logits = [h_fwd, h_bwd] @ W_out + b_out, then softmax.
// ============================================================================
__global__ void __launch_bounds__(256) out_kernel(
    const float* __restrict__ W_out, const float* __restrict__ b_out,
    float* __restrict__ out)
{
    __shared__ float ws[2 * HN * NLAB];     // 20 KB
    __shared__ float red[4][BATCHN][NLAB];  // 10 KB
    const int tid = threadIdx.x;
    for (int i = tid; i < 2 * HN * NLAB; i += 256) ws[i] = W_out[i];
    __syncthreads();

    const int q   = tid >> 6;
    const int b   = tid & 63;
    const int dir = q >> 1;
    const int ub  = (q & 1) * 128;

    float acc[NLAB];
#pragma unroll
    for (int l = 0; l < NLAB; ++l) acc[l] = 0.0f;

#pragma unroll 8
    for (int uu = 0; uu < 128; ++uu) {
        int u = ub + uu;
        float hv = g_h[dir][u][b];
        const float* w = ws + (dir * HN + u) * NLAB;
#pragma unroll
        for (int l = 0; l < NLAB; ++l) acc[l] += hv * w[l];
    }
#pragma unroll
    for (int l = 0; l < NLAB; ++l) red[q][b][l] = acc[l];
    __syncthreads();

    if (tid < BATCHN) {
        float a[NLAB];
#pragma unroll
        for (int l = 0; l < NLAB; ++l)
            a[l] = b_out[l] + red[0][tid][l] + red[1][tid][l]
                 + red[2][tid][l] + red[3][tid][l];
        float m = a[0];
#pragma unroll
        for (int l = 1; l < NLAB; ++l) m = fmaxf(m, a[l]);
        float s = 0.0f;
#pragma unroll
        for (int l = 0; l < NLAB; ++l) { a[l] = expf(a[l] - m); s += a[l]; }
        float inv = 1.0f / s;
#pragma unroll
        for (int l = 0; l < NLAB; ++l) out[tid * NLAB + l] = a[l] * inv;
    }
}

// ============================================================================
extern "C" void kernel_launch(void* const* d_in, const int* in_sizes, int n_in,
                              void* d_out, int out_size)
{
    const int*   tokens = (const int*)  d_in[0];
    const float* emb    = (const float*)d_in[1];
    const float* Wx_f   = (const float*)d_in[2];
    const float* Wh_f   = (const float*)d_in[3];
    const float* b_f    = (const float*)d_in[4];
    const float* Wx_b   = (const float*)d_in[5];
    const float* Wh_b   = (const float*)d_in[6];
    const float* b_b    = (const float*)d_in[7];
    const float* W_out  = (const float*)d_in[8];
    const float* b_out  = (const float*)d_in[9];
    float* out = (float*)d_out;

    const int lstm_smem = 131072 + 16384 + 2048 + 4096;   // 153600 B = 150 KB
    cudaFuncSetAttribute(lstm_kernel,
                         cudaFuncAttributeMaxDynamicSharedMemorySize, lstm_smem);

    zx_gemm_kernel<<<4096, 256>>>(tokens, emb, Wx_f, b_f, Wx_b, b_b);
    lstm_kernel<<<128, 256, lstm_smem>>>(Wh_f, Wh_b);
    out_kernel<<<1, 256>>>(W_out, b_out, out);
}